// round 13
// baseline (speedup 1.0000x reference)
#include <cuda_runtime.h>
#include <stdint.h>

// Problem constants
#define NT    4000
#define NS    16
#define NR    512
#define NCOL  (NS * NR)          // 8192 columns
#define NSEG  40
#define SEG_LEN (NT / NSEG)      // 100
#define TPB   256
#define XBLK  (NCOL / TPB)       // 32
#define FIN_BLOCKS (NCOL / TPB)  // 32

// Per-column packed argmax accumulators (0 = x, 1 = y), merged via atomicMax.
// key = (float_bits(|v|max) << 32) | ~t : u64 max -> larger |v| wins; on ties
// the larger ~t (= smaller t) wins, matching jnp.argmax. Keys are always > 0,
// so zero is a valid identity; finalize_kernel self-resets for graph replay.
__device__ unsigned long long g_best[2][NCOL];
__device__ unsigned long long g_accum;
__device__ unsigned int       g_done;

// Kernel 1: grid (XBLK, NSEG) = 1280 blocks, 327,680 threads.
// Thread (col, seg) scans SEG_LEN=100 time samples of ONE column for both
// x and y with scalar loads: each warp request is exactly one 128B line,
// unroll 8 -> 16 independent lines in flight per warp at ~34 regs. 1280
// blocks = 8.6/SM removes the grid-occupancy cap seen at 640 blocks
// (occ 54.3% in the R10 profile).
__global__ __launch_bounds__(TPB) void seg_argmax_kernel(
    const float* __restrict__ x, const float* __restrict__ y)
{
    const int col = blockIdx.x * TPB + threadIdx.x;   // 0..NCOL-1
    const int t0  = blockIdx.y * SEG_LEN;

    const float* __restrict__ px = x + (size_t)t0 * NCOL + col;
    const float* __restrict__ py = y + (size_t)t0 * NCOL + col;

    float mx = -1.0f, my = -1.0f;
    int   ix = t0,    iy = t0;

    #pragma unroll 8
    for (int i = 0; i < SEG_LEN; ++i) {
        const float vx = fabsf(px[(size_t)i * NCOL]);
        const float vy = fabsf(py[(size_t)i * NCOL]);
        const int t = t0 + i;
        if (vx > mx) ix = t;
        mx = fmaxf(vx, mx);
        if (vy > my) iy = t;
        my = fmaxf(vy, my);
    }

    atomicMax(&g_best[0][col],
        ((unsigned long long)__float_as_uint(mx) << 32) | (unsigned int)~ix);
    atomicMax(&g_best[1][col],
        ((unsigned long long)__float_as_uint(my) << 32) | (unsigned int)~iy);
}

// Kernel 2: O(1) per thread. Read per-column winners, self-reset them for the
// next graph replay, exact integer MSE, one atomicAdd per block, ticketed
// last block writes the scalar and resets the accumulator.
__global__ __launch_bounds__(TPB) void finalize_kernel(float* __restrict__ out)
{
    const int col = blockIdx.x * TPB + threadIdx.x;

    const unsigned long long bx = g_best[0][col];
    const unsigned long long by = g_best[1][col];
    g_best[0][col] = 0ull;
    g_best[1][col] = 0ull;

    const int tx = (int)(~(unsigned int)bx);
    const int ty = (int)(~(unsigned int)by);
    const long long d = (long long)tx - (long long)ty;
    unsigned long long sq = (unsigned long long)(d * d);

    #pragma unroll
    for (int off = 16; off > 0; off >>= 1)
        sq += __shfl_down_sync(0xffffffffu, sq, off);

    __shared__ unsigned long long warp_sums[TPB / 32];
    const int lane = threadIdx.x & 31;
    const int wid  = threadIdx.x >> 5;
    if (lane == 0) warp_sums[wid] = sq;
    __syncthreads();

    if (wid == 0) {
        unsigned long long v = (lane < TPB / 32) ? warp_sums[lane] : 0ull;
        #pragma unroll
        for (int off = 4; off > 0; off >>= 1)
            v += __shfl_down_sync(0xffffffffu, v, off);
        if (lane == 0) {
            atomicAdd(&g_accum, v);
            __threadfence();
            const unsigned int ticket = atomicAdd(&g_done, 1u);
            if (ticket == (unsigned int)(FIN_BLOCKS - 1)) {
                const unsigned long long total = atomicAdd(&g_accum, 0ull);
                out[0] = (float)((double)total / (double)NCOL);
                __threadfence();
                g_accum = 0ull;
                g_done  = 0u;
            }
        }
    }
}

extern "C" void kernel_launch(void* const* d_in, const int* in_sizes, int n_in,
                              void* d_out, int out_size)
{
    const float* x = (const float*)d_in[0];
    const float* y = (const float*)d_in[1];
    float* out = (float*)d_out;

    dim3 grid1(XBLK, NSEG);
    seg_argmax_kernel<<<grid1, TPB>>>(x, y);
    finalize_kernel<<<FIN_BLOCKS, TPB>>>(out);
}

// round 14
// speedup vs baseline: 1.1278x; 1.1278x over previous
#include <cuda_runtime.h>
#include <stdint.h>

// Problem constants
#define NT    4000
#define NS    16
#define NR    512
#define NCOL  (NS * NR)          // 8192 columns
#define TPB   256
#define XBLK  (NCOL / TPB)       // 32 column-blocks
#define NSEG  37                 // 36 segs of 108 + 1 seg of 112 (= 4000)
#define SEG_LEN 108
#define NBLK  (XBLK * NSEG)      // 1184 = 148 SMs x 8 blocks: ONE full wave
#define FIN_BLOCKS (NCOL / TPB)  // 32

// Per-column packed argmax accumulators (0 = x, 1 = y), merged via atomicMax.
// key = (float_bits(|v|max) << 32) | ~t : u64 max -> larger |v| wins; on ties
// the larger ~t (= smaller t) wins, matching jnp.argmax. Keys are always > 0,
// so zero is a valid identity; finalize_kernel self-resets for graph replay.
__device__ unsigned long long g_best[2][NCOL];
__device__ unsigned long long g_accum;
__device__ unsigned int       g_done;

// Kernel 1: 1184 blocks, exactly 8 resident blocks per SM (64 warps/SM),
// single wave, perfect balance. Thread (col, seg) scans its segment of ONE
// column for both x and y with scalar loads: each warp request is one 128B
// line; unroll 8 -> 16 independent lines in flight per warp.
// __launch_bounds__(TPB, 8) caps registers at 32 so 8 blocks/SM truly fit.
__global__ __launch_bounds__(TPB, 8) void seg_argmax_kernel(
    const float* __restrict__ x, const float* __restrict__ y)
{
    const int tile = blockIdx.x;
    const int col  = (tile & (XBLK - 1)) * TPB + threadIdx.x;  // 0..NCOL-1
    const int seg  = tile >> 5;                                // 0..36
    const int t0   = seg * SEG_LEN;
    const int len  = (seg == NSEG - 1) ? (NT - t0) : SEG_LEN;  // 108 or 112

    const float* __restrict__ px = x + (size_t)t0 * NCOL + col;
    const float* __restrict__ py = y + (size_t)t0 * NCOL + col;

    float mx = -1.0f, my = -1.0f;
    int   ix = t0,    iy = t0;

    #pragma unroll 8
    for (int i = 0; i < len; ++i) {
        const float vx = fabsf(px[(size_t)i * NCOL]);
        const float vy = fabsf(py[(size_t)i * NCOL]);
        const int t = t0 + i;
        if (vx > mx) ix = t;
        mx = fmaxf(vx, mx);
        if (vy > my) iy = t;
        my = fmaxf(vy, my);
    }

    atomicMax(&g_best[0][col],
        ((unsigned long long)__float_as_uint(mx) << 32) | (unsigned int)~ix);
    atomicMax(&g_best[1][col],
        ((unsigned long long)__float_as_uint(my) << 32) | (unsigned int)~iy);
}

// Kernel 2: O(1) per thread. Read per-column winners, self-reset them for the
// next graph replay, exact integer MSE, one atomicAdd per block, ticketed
// last block writes the scalar and resets the accumulator.
__global__ __launch_bounds__(TPB) void finalize_kernel(float* __restrict__ out)
{
    const int col = blockIdx.x * TPB + threadIdx.x;

    const unsigned long long bx = g_best[0][col];
    const unsigned long long by = g_best[1][col];
    g_best[0][col] = 0ull;
    g_best[1][col] = 0ull;

    const int tx = (int)(~(unsigned int)bx);
    const int ty = (int)(~(unsigned int)by);
    const long long d = (long long)tx - (long long)ty;
    unsigned long long sq = (unsigned long long)(d * d);

    #pragma unroll
    for (int off = 16; off > 0; off >>= 1)
        sq += __shfl_down_sync(0xffffffffu, sq, off);

    __shared__ unsigned long long warp_sums[TPB / 32];
    const int lane = threadIdx.x & 31;
    const int wid  = threadIdx.x >> 5;
    if (lane == 0) warp_sums[wid] = sq;
    __syncthreads();

    if (wid == 0) {
        unsigned long long v = (lane < TPB / 32) ? warp_sums[lane] : 0ull;
        #pragma unroll
        for (int off = 4; off > 0; off >>= 1)
            v += __shfl_down_sync(0xffffffffu, v, off);
        if (lane == 0) {
            atomicAdd(&g_accum, v);
            __threadfence();
            const unsigned int ticket = atomicAdd(&g_done, 1u);
            if (ticket == (unsigned int)(FIN_BLOCKS - 1)) {
                const unsigned long long total = atomicAdd(&g_accum, 0ull);
                out[0] = (float)((double)total / (double)NCOL);
                __threadfence();
                g_accum = 0ull;
                g_done  = 0u;
            }
        }
    }
}

extern "C" void kernel_launch(void* const* d_in, const int* in_sizes, int n_in,
                              void* d_out, int out_size)
{
    const float* x = (const float*)d_in[0];
    const float* y = (const float*)d_in[1];
    float* out = (float*)d_out;

    seg_argmax_kernel<<<NBLK, TPB>>>(x, y);
    finalize_kernel<<<FIN_BLOCKS, TPB>>>(out);
}